// round 5
// baseline (speedup 1.0000x reference)
#include <cuda_runtime.h>
#include <math.h>

#define BQ   1024
#define VN   6890
#define JN   24
#define NBT  10
#define PP   207
#define N3   20670     // VN*3
#define KE   224       // padded K: 207 pose_feature + 10 betas + 7 zeros
#define VPITCH 20736   // padded N (324*64)
#define NJOUT 61       // 24 + 11 + 9 + 17

// ---------------- device scratch (allocation-free) ----------------
__device__ float g_JST[JN * 33];                 // folded regressor: [j][k*11 + l], l<10 shapedirs, l==10 template
__device__ float g_pfe[BQ * KE];                 // A matrix rows
__device__ float g_pde[KE * VPITCH];             // B matrix (posedirs | shapedirs^T | 0)
__device__ float g_vposed[(size_t)BQ * VPITCH];  // GEMM output
__device__ float g_A[BQ * JN * 12];              // rel transforms 3x4

__constant__ int c_parents[24] = {-1,0,0,0,1,2,3,4,5,6,7,8,9,9,9,12,13,14,16,17,18,19,20,21};

// ---------------- K0a: fold J_regressor against template/shapedirs ----------------
__global__ void k0_fold(const float* __restrict__ Jreg,
                        const float* __restrict__ shapedirs,
                        const float* __restrict__ v_template) {
    int j = blockIdx.x;                       // 0..23
    int warp = threadIdx.x >> 5, lane = threadIdx.x & 31;
    for (int o = warp; o < 33; o += 8) {
        int k = o / 11, l = o % 11;
        float acc = 0.f;
        for (int v = lane; v < VN; v += 32) {
            float jr = Jreg[j * VN + v];
            float x  = (l < 10) ? shapedirs[v * 30 + k * 10 + l] : v_template[v * 3 + k];
            acc += jr * x;
        }
        #pragma unroll
        for (int s = 16; s; s >>= 1) acc += __shfl_down_sync(0xffffffffu, acc, s);
        if (lane == 0) g_JST[j * 33 + k * 11 + l] = acc;
    }
}

// ---------------- K0b: build extended B matrix ----------------
__global__ void k0_pde(const float* __restrict__ posedirs,
                       const float* __restrict__ shapedirs) {
    int idx = blockIdx.x * blockDim.x + threadIdx.x;    // exact grid
    int row = idx / VPITCH;
    int col = idx - row * VPITCH;
    float val = 0.f;
    if (col < N3) {
        if (row < PP) {
            val = posedirs[row * N3 + col];
        } else if (row < PP + NBT) {
            int v = col / 3, k = col - v * 3, l = row - PP;
            val = shapedirs[v * 30 + k * 10 + l];
        }
    }
    g_pde[idx] = val;
}

// ---------------- K1: Rodrigues + Jrest + kinematic chain (1 warp/batch) ----------------
__global__ void k1_pose(const float* __restrict__ betas,
                        const float* __restrict__ poses,
                        float* __restrict__ out_joints) {   // base of joints section of d_out
    int b = blockIdx.x;
    int lane = threadIdx.x;                 // blockDim = 32
    __shared__ float sh_b[NBT];
    __shared__ float sh_J[JN * 3];
    __shared__ float sh_T[JN * 12];
    __shared__ float sh_G[JN * 12];

    if (lane < NBT) sh_b[lane] = betas[b * NBT + lane];
    __syncthreads();

    float R[9];
    if (lane < JN) {
        int j = lane;
        float p0 = poses[b * 72 + j * 3 + 0];
        float p1 = poses[b * 72 + j * 3 + 1];
        float p2 = poses[b * 72 + j * 3 + 2];
        const float e = 1e-8f;
        float a0 = p0 + e, a1 = p1 + e, a2 = p2 + e;
        float ang = sqrtf(a0 * a0 + a1 * a1 + a2 * a2);
        float inv = 1.0f / ang;
        float rx = p0 * inv, ry = p1 * inv, rz = p2 * inv;
        float c = cosf(ang), s = sinf(ang), oc = 1.0f - c;
        R[0] = 1.f - oc * (ry * ry + rz * rz);
        R[1] = -s * rz + oc * rx * ry;
        R[2] =  s * ry + oc * rx * rz;
        R[3] =  s * rz + oc * rx * ry;
        R[4] = 1.f - oc * (rx * rx + rz * rz);
        R[5] = -s * rx + oc * ry * rz;
        R[6] = -s * ry + oc * rx * rz;
        R[7] =  s * rx + oc * ry * rz;
        R[8] = 1.f - oc * (rx * rx + ry * ry);

        if (j >= 1) {
            float* pf = &g_pfe[(size_t)b * KE + (j - 1) * 9];
            #pragma unroll
            for (int i = 0; i < 9; i++)
                pf[i] = R[i] - ((i == 0 || i == 4 || i == 8) ? 1.f : 0.f);
        }
        // Jrest[b][j] from folded regressor
        #pragma unroll
        for (int k = 0; k < 3; k++) {
            float acc = g_JST[j * 33 + k * 11 + 10];
            #pragma unroll
            for (int l = 0; l < NBT; l++) acc += sh_b[l] * g_JST[j * 33 + k * 11 + l];
            sh_J[j * 3 + k] = acc;
        }
    }
    if (lane < NBT)               g_pfe[(size_t)b * KE + PP + lane] = sh_b[lane];
    if (lane >= NBT && lane < 17) g_pfe[(size_t)b * KE + PP + lane] = 0.f;
    __syncthreads();

    if (lane < JN) {
        int j = lane;
        float r0 = sh_J[j * 3 + 0], r1 = sh_J[j * 3 + 1], r2 = sh_J[j * 3 + 2];
        if (j > 0) {
            int p = c_parents[j];
            r0 -= sh_J[p * 3 + 0]; r1 -= sh_J[p * 3 + 1]; r2 -= sh_J[p * 3 + 2];
        }
        sh_T[j*12+0]=R[0]; sh_T[j*12+1]=R[1]; sh_T[j*12+ 2]=R[2]; sh_T[j*12+ 3]=r0;
        sh_T[j*12+4]=R[3]; sh_T[j*12+5]=R[4]; sh_T[j*12+ 6]=R[5]; sh_T[j*12+ 7]=r1;
        sh_T[j*12+8]=R[6]; sh_T[j*12+9]=R[7]; sh_T[j*12+10]=R[8]; sh_T[j*12+11]=r2;
    }
    __syncthreads();

    if (lane < 12) sh_G[lane] = sh_T[lane];     // chain[0]
    __syncthreads();
    for (int i = 1; i < JN; i++) {
        if (lane < 12) {
            int p = c_parents[i];
            int r = lane >> 2, cc = lane & 3;
            const float* Gp = &sh_G[p * 12 + r * 4];
            const float* Ti = &sh_T[i * 12];
            float v = Gp[0] * Ti[0 * 4 + cc] + Gp[1] * Ti[1 * 4 + cc] + Gp[2] * Ti[2 * 4 + cc];
            if (cc == 3) v += Gp[3];
            sh_G[i * 12 + lane] = v;
        }
        __syncthreads();
    }

    if (lane < JN) {
        int j = lane;
        const float* G = &sh_G[j * 12];
        float j0 = sh_J[j * 3 + 0], j1 = sh_J[j * 3 + 1], j2 = sh_J[j * 3 + 2];
        #pragma unroll
        for (int r = 0; r < 3; r++) {
            size_t base = ((size_t)b * JN + j) * 12 + (size_t)r * 4;
            float g0 = G[r*4+0], g1 = G[r*4+1], g2 = G[r*4+2], g3 = G[r*4+3];
            g_A[base + 0] = g0;
            g_A[base + 1] = g1;
            g_A[base + 2] = g2;
            g_A[base + 3] = g3 - (g0 * j0 + g1 * j1 + g2 * j2);
            out_joints[((size_t)b * NJOUT + j) * 3 + r] = g3;   // J_transformed
        }
    }
}

// ---------------- K2: fused SGEMM  v_posed = pfe @ pde + v_template ----------------
__global__ void __launch_bounds__(256)
k2_gemm(const float* __restrict__ v_template) {
    __shared__ float As[16][64];
    __shared__ float Bs[16][64];
    int tid = threadIdx.x;
    int tx = tid & 15, ty = tid >> 4;
    int m0 = blockIdx.y * 64;
    int n0 = blockIdx.x * 64;

    int ar = tid >> 2;            // 0..63
    int ac = (tid & 3) * 4;       // 0,4,8,12
    int br = tid >> 4;            // 0..15
    int bc = (tid & 15) * 4;      // 0..60

    float acc[4][4];
    #pragma unroll
    for (int i = 0; i < 4; i++)
        #pragma unroll
        for (int j = 0; j < 4; j++) acc[i][j] = 0.f;

    for (int kt = 0; kt < KE; kt += 16) {
        float4 a = *(const float4*)&g_pfe[(size_t)(m0 + ar) * KE + kt + ac];
        As[ac + 0][ar] = a.x; As[ac + 1][ar] = a.y;
        As[ac + 2][ar] = a.z; As[ac + 3][ar] = a.w;
        float4 bv = *(const float4*)&g_pde[(size_t)(kt + br) * VPITCH + n0 + bc];
        *(float4*)&Bs[br][bc] = bv;
        __syncthreads();
        #pragma unroll
        for (int k = 0; k < 16; k++) {
            float4 av = *(const float4*)&As[k][ty * 4];
            float4 bw = *(const float4*)&Bs[k][tx * 4];
            float aa[4] = {av.x, av.y, av.z, av.w};
            float bb[4] = {bw.x, bw.y, bw.z, bw.w};
            #pragma unroll
            for (int i = 0; i < 4; i++)
                #pragma unroll
                for (int j = 0; j < 4; j++) acc[i][j] += aa[i] * bb[j];
        }
        __syncthreads();
    }

    #pragma unroll
    for (int i = 0; i < 4; i++) {
        int m = m0 + ty * 4 + i;
        #pragma unroll
        for (int j = 0; j < 4; j++) {
            int n = n0 + tx * 4 + j;
            float bias = (n < N3) ? v_template[n] : 0.f;
            g_vposed[(size_t)m * VPITCH + n] = acc[i][j] + bias;
        }
    }
}

// ---------------- K3: skinning, 4 batches per block ----------------
#define NBPB 4
__global__ void __launch_bounds__(256)
k3_skin(const float* __restrict__ lbs_weights,
        float* __restrict__ out_verts) {
    __shared__ float sA[NBPB][JN * 12];
    int b0 = blockIdx.y * NBPB;
    int tid = threadIdx.x;
    for (int i = tid; i < NBPB * JN * 12; i += 256)
        sA[i / (JN * 12)][i % (JN * 12)] = g_A[(size_t)(b0 + i / (JN * 12)) * (JN * 12) + i % (JN * 12)];
    __syncthreads();

    int v = blockIdx.x * 256 + tid;
    if (v >= VN) return;

    float w[JN];
    const float4* wp = (const float4*)&lbs_weights[(size_t)v * JN];
    #pragma unroll
    for (int q = 0; q < 6; q++) {
        float4 t = wp[q];
        w[q*4+0] = t.x; w[q*4+1] = t.y; w[q*4+2] = t.z; w[q*4+3] = t.w;
    }

    #pragma unroll
    for (int bb = 0; bb < NBPB; bb++) {
        int b = b0 + bb;
        float T[12];
        #pragma unroll
        for (int r = 0; r < 12; r++) T[r] = 0.f;
        #pragma unroll
        for (int j = 0; j < JN; j++) {
            float wj = w[j];
            #pragma unroll
            for (int r = 0; r < 12; r++) T[r] += wj * sA[bb][j * 12 + r];
        }
        size_t vb = (size_t)b * VPITCH + (size_t)v * 3;
        float vx = g_vposed[vb + 0], vy = g_vposed[vb + 1], vz = g_vposed[vb + 2];
        float ox = T[0]*vx + T[1]*vy + T[2]*vz  + T[3];
        float oy = T[4]*vx + T[5]*vy + T[6]*vz  + T[7];
        float oz = T[8]*vx + T[9]*vy + T[10]*vz + T[11];
        size_t ob = ((size_t)b * VN + v) * 3;
        out_verts[ob + 0] = ox;
        out_verts[ob + 1] = oy;
        out_verts[ob + 2] = oz;
    }
}

// ---------------- K4: extra9 + h36m17 joint regression ----------------
#define CH 512
__global__ void __launch_bounds__(256)
k4_reg(const float* __restrict__ Je9,
       const float* __restrict__ Jh17,
       const float* __restrict__ verts,      // d_out verts section
       float* __restrict__ out_joints) {
    __shared__ float sv[CH * 3];
    __shared__ float red[256];
    int b = blockIdx.x;
    int tid = threadIdx.x;

    int p = tid / 3;           // (jj,k) pair 0..77
    int s = tid % 3;           // v slice
    int jj = p / 3, k = p % 3;
    const float* Jr = (jj < 9) ? &Je9[(size_t)jj * VN] : &Jh17[(size_t)(jj - 9) * VN];

    float acc = 0.f;
    for (int v0 = 0; v0 < VN; v0 += CH) {
        int cnt = VN - v0; if (cnt > CH) cnt = CH;
        for (int i = tid; i < cnt * 3; i += 256)
            sv[i] = verts[((size_t)b * VN + v0) * 3 + i];
        __syncthreads();
        if (tid < 234) {
            for (int v = s; v < cnt; v += 3)
                acc += Jr[v0 + v] * sv[v * 3 + k];
        }
        __syncthreads();
    }
    red[tid] = acc;
    __syncthreads();
    if (tid < 78) {
        float total = red[tid * 3] + red[tid * 3 + 1] + red[tid * 3 + 2];
        int jjo = tid / 3, ko = tid % 3;
        out_joints[((size_t)b * NJOUT + 35 + jjo) * 3 + ko] = total;
    }
}

// ---------------- K5: extra11 gather ----------------
__global__ void k5_gather(const int* __restrict__ idxs,
                          const float* __restrict__ verts,
                          float* __restrict__ out_joints) {
    int t = blockIdx.x * blockDim.x + threadIdx.x;   // exact grid: BQ*11*3
    int b = t / 33;
    int r = t - b * 33;
    int i = r / 3, k = r % 3;
    int v = idxs[i];
    out_joints[((size_t)b * NJOUT + 24 + i) * 3 + k] = verts[((size_t)b * VN + v) * 3 + k];
}

// ---------------- launch ----------------
extern "C" void kernel_launch(void* const* d_in, const int* in_sizes, int n_in,
                              void* d_out, int out_size) {
    (void)in_sizes; (void)n_in; (void)out_size;
    const float* betas      = (const float*)d_in[0];
    const float* poses      = (const float*)d_in[1];
    const int*   ext_idx    = (const int*)  d_in[2];
    const float* v_template = (const float*)d_in[3];
    const float* shapedirs  = (const float*)d_in[4];
    const float* posedirs   = (const float*)d_in[5];
    const float* Jreg       = (const float*)d_in[6];
    const float* lbs_w      = (const float*)d_in[7];
    const float* Je9        = (const float*)d_in[8];
    const float* Jh17       = (const float*)d_in[9];

    float* out_verts  = (float*)d_out;
    float* out_joints = out_verts + (size_t)BQ * VN * 3;

    k0_fold<<<JN, 256>>>(Jreg, shapedirs, v_template);
    k0_pde<<<(KE * VPITCH) / 256, 256>>>(posedirs, shapedirs);
    k1_pose<<<BQ, 32>>>(betas, poses, out_joints);
    k2_gemm<<<dim3(VPITCH / 64, BQ / 64), 256>>>(v_template);
    k3_skin<<<dim3((VN + 255) / 256, BQ / NBPB), 256>>>(lbs_w, out_verts);
    k4_reg<<<BQ, 256>>>(Je9, Jh17, out_verts, out_joints);
    k5_gather<<<(BQ * 11 * 3) / 256, 256>>>(ext_idx, out_verts, out_joints);
}